// round 12
// baseline (speedup 1.0000x reference)
#include <cuda_runtime.h>
#include <cuda_fp16.h>
#include <math.h>
#include <stdint.h>

// ---------------- problem constants ----------------
#define NTOK 8192
#define DDIM 1024
#define HDIM 4096
#define ODIM 1024
#define NEXP 8
#define TOPK 3
#define NSLOT (NTOK * TOPK)

// ---------------- static device scratch (compact slot layout) ----------------
// g_meta[0..NEXP)      = per-expert counts (gate atomics)
// g_meta[NEXP..2*NEXP) = per-expert scatter cursors
__device__ int    g_meta[2 * NEXP];
__device__ int    g_topk_e[NTOK * TOPK];
__device__ float  g_topk_w[NTOK * TOPK];
__device__ int    g_slot_token[NSLOT];
__device__ float  g_slot_weight[NSLOT];
__device__ __half g_h[(size_t)NSLOT * HDIM];   // 201.3 MB fp16 h activations

// ---------------- helpers ----------------
__device__ __forceinline__ uint32_t smem_u32(const void* p) {
    uint32_t a;
    asm("{ .reg .u64 t; cvta.to.shared.u64 t, %1; cvt.u32.u64 %0, t; }"
        : "=r"(a) : "l"(p));
    return a;
}

__device__ __forceinline__ uint32_t pack_h2(float lo, float hi) {
    __half2 h = __floats2half2_rn(lo, hi);
    return *reinterpret_cast<uint32_t*>(&h);
}

__device__ __forceinline__ void ldsm_x4(uint32_t addr, uint32_t& r0, uint32_t& r1,
                                        uint32_t& r2, uint32_t& r3) {
    asm volatile("ldmatrix.sync.aligned.m8n8.x4.shared.b16 {%0,%1,%2,%3}, [%4];"
                 : "=r"(r0), "=r"(r1), "=r"(r2), "=r"(r3) : "r"(addr));
}

__device__ __forceinline__ void ldsm_x4_t(uint32_t addr, uint32_t& r0, uint32_t& r1,
                                          uint32_t& r2, uint32_t& r3) {
    asm volatile("ldmatrix.sync.aligned.m8n8.x4.trans.shared.b16 {%0,%1,%2,%3}, [%4];"
                 : "=r"(r0), "=r"(r1), "=r"(r2), "=r"(r3) : "r"(addr));
}

__device__ __forceinline__ void mma_f16(float* d, const uint32_t* a, const uint32_t* b) {
    asm volatile(
        "mma.sync.aligned.m16n8k16.row.col.f32.f16.f16.f32 "
        "{%0,%1,%2,%3}, {%4,%5,%6,%7}, {%8,%9}, {%0,%1,%2,%3};\n"
        : "+f"(d[0]), "+f"(d[1]), "+f"(d[2]), "+f"(d[3])
        : "r"(a[0]), "r"(a[1]), "r"(a[2]), "r"(a[3]),
          "r"(b[0]), "r"(b[1]));
}

// expert base offset = sum of counts of lower-indexed experts
__device__ __forceinline__ int expert_base(int e) {
    int b = 0;
#pragma unroll
    for (int i = 0; i < NEXP; i++)
        if (i < e) b += g_meta[i];
    return b;
}

// ---------------- gate: one warp per token, float4 x-loads (MLP=8) ----------------
__global__ void gate_kernel(const float* __restrict__ x,
                            const float* __restrict__ gw,
                            const float* __restrict__ gb) {
    int tok  = (blockIdx.x * blockDim.x + threadIdx.x) >> 5;
    int lane = threadIdx.x & 31;
    if (tok >= NTOK) return;

    const float4* xr4 = reinterpret_cast<const float4*>(x + (size_t)tok * DDIM);

    // batch all 8 x row-loads first: 128B/lane in flight, hides DRAM latency
    float4 xv[8];
#pragma unroll
    for (int j = 0; j < 8; j++) xv[j] = xr4[j * 32 + lane];

    float part[NEXP];
#pragma unroll
    for (int e = 0; e < NEXP; e++) part[e] = 0.0f;

#pragma unroll
    for (int j = 0; j < 8; j++) {
        const int d0 = j * 128 + lane * 4;
        const float xq[4] = { xv[j].x, xv[j].y, xv[j].z, xv[j].w };
#pragma unroll
        for (int q = 0; q < 4; q++) {
            const float4* gp = reinterpret_cast<const float4*>(gw + (size_t)(d0 + q) * NEXP);
            float4 a = gp[0];
            float4 b = gp[1];
            part[0] += xq[q] * a.x; part[1] += xq[q] * a.y;
            part[2] += xq[q] * a.z; part[3] += xq[q] * a.w;
            part[4] += xq[q] * b.x; part[5] += xq[q] * b.y;
            part[6] += xq[q] * b.z; part[7] += xq[q] * b.w;
        }
    }
#pragma unroll
    for (int off = 16; off > 0; off >>= 1)
#pragma unroll
        for (int e = 0; e < NEXP; e++)
            part[e] += __shfl_xor_sync(0xffffffffu, part[e], off);

    if (lane == 0) {
        float s[NEXP];
#pragma unroll
        for (int e = 0; e < NEXP; e++) s[e] = part[e] + gb[e];

        int id[TOPK];
        bool used[NEXP];
#pragma unroll
        for (int e = 0; e < NEXP; e++) used[e] = false;
#pragma unroll
        for (int k = 0; k < TOPK; k++) {
            float best = -1e30f;
            int bi = 0;
#pragma unroll
            for (int e = 0; e < NEXP; e++)
                if (!used[e] && s[e] > best) { best = s[e]; bi = e; }
            used[bi] = true;
            id[k] = bi;
        }

        float mx = s[0];
#pragma unroll
        for (int e = 1; e < NEXP; e++) mx = fmaxf(mx, s[e]);
        float p[NEXP], tot = 0.0f;
#pragma unroll
        for (int e = 0; e < NEXP; e++) { p[e] = expf(s[e] - mx); tot += p[e]; }
        float inv = 1.0f / tot;
        float msum = (p[id[0]] + p[id[1]] + p[id[2]]) * inv;
        float den = msum + 1e-8f;

#pragma unroll
        for (int k = 0; k < TOPK; k++) {
            int e = id[k];
            g_topk_e[tok * TOPK + k] = e;
            g_topk_w[tok * TOPK + k] = (p[e] * inv) / den;
            atomicAdd(&g_meta[e], 1);
        }
    }
}

// ---------------- scatter tokens into compact per-expert lists ----------------
// Offsets computed inline from g_meta counts (no separate offsets kernel).
__global__ void scatter_kernel() {
    int t = blockIdx.x * blockDim.x + threadIdx.x;
    if (t >= NTOK) return;
#pragma unroll
    for (int k = 0; k < TOPK; k++) {
        int e = g_topk_e[t * TOPK + k];
        int pos = atomicAdd(&g_meta[NEXP + e], 1);
        int i = expert_base(e) + pos;
        g_slot_token[i] = t;
        g_slot_weight[i] = g_topk_w[t * TOPK + k];
    }
}

// ---------------- fp16 mma.sync grouped GEMM (proven R7 configuration) ----------------
// CTA 128x128, 4 warps of 64x64, K-tile 32, double-buffered, ldmatrix fragments.
// occ=2 per SM. GEMM2 uses KSPLIT=2 with atomic combine.
#define BM 128
#define BN 128
#define BK 32
#define SA 40     // A row stride (halves)
#define SB 136    // B row stride (halves)
#define A_STAGE_B (BM * SA * 2)              // 10240 bytes
#define B_STAGE_B (BK * SB * 2)              // 8704 bytes
#define STAGE_B (A_STAGE_B + B_STAGE_B)      // 18944 bytes
#define EPI_STRIDE 66
#define SMEM_GEMM_BYTES (4 * 64 * EPI_STRIDE * 4)   // 67584 (> 2*STAGE_B = 37888)

template <int KDIM, int NDIM, bool FIRST, int KSPLIT>
__global__ __launch_bounds__(128, 2) void moe_gemm_kernel(
    const float* __restrict__ A,     // x when FIRST (g_h otherwise)
    const float* __restrict__ B,     // w1 / w2  [E, KDIM, NDIM]
    const float* __restrict__ bias,  // [E, NDIM]
    float* __restrict__ out)
{
    const int zz = blockIdx.z;
    const int e  = zz / KSPLIT;
    const int ks = zz % KSPLIT;
    const int cnt = g_meta[e];
    const int m0 = blockIdx.y * BM;
    if (m0 >= cnt) return;
    const int base = expert_base(e);
    const int n0 = blockIdx.x * BN;
    const int kbeg = ks * (KDIM / KSPLIT);

    extern __shared__ char dsm[];
    __shared__ int stok[BM];
    const uint32_t sb = smem_u32(dsm);

    const int tid  = threadIdx.x;
    const int wid  = tid >> 5;
    const int lane = tid & 31;
    const int gq = lane >> 2;   // 0..7
    const int tg = lane & 3;    // 0..3
    const int wm = wid >> 1;    // 0..1
    const int wn = wid & 1;     // 0..1

    if (FIRST) {
        if (tid < BM) {
            int r = m0 + tid;
            stok[tid] = (r < cnt) ? g_slot_token[base + r] : -1;
        }
    }
    __syncthreads();

    const float*  Apf = A;
    const __half* Aph = g_h;
    const float*  Bp  = B + (size_t)e * KDIM * NDIM;

    // staging maps (128 threads)
    const int a_r1 = tid >> 3;            // FIRST: row in 16-row group (0..15)
    const int a_c1 = (tid & 7) * 4;       // FIRST: k offset (floats)
    const int a_r2 = tid >> 2;            // !FIRST: row in 32-row group (0..31)
    const int a_c2 = (tid & 3) * 8;       // !FIRST: k offset (halves)
    const int b_r  = tid >> 4;            // 0..7
    const int b_c  = (tid & 15) * 4;      // 0..60

    // ldmatrix lane offsets (bytes within stage)
    const uint32_t a_lm = (uint32_t)(((wm * 64 + (lane & 15)) * SA + ((lane >> 4) << 3)) * 2);
    const uint32_t b_lm = (uint32_t)(((lane & 15) * SB + wn * 64 + ((lane >> 4) << 3)) * 2);

    float acc[4][8][4];
#pragma unroll
    for (int mi = 0; mi < 4; mi++)
#pragma unroll
        for (int ni = 0; ni < 8; ni++)
#pragma unroll
            for (int r = 0; r < 4; r++) acc[mi][ni][r] = 0.0f;

    // staging registers
    float4 la1[8];    // FIRST: 8 rounds x 16 rows
    uint4  la2[4];    // !FIRST: 4 rounds x 32 rows
    float4 lb[4][2];  // B: 4 k-rounds (8 rows) x 2 col-halves

    auto load_tile = [&](int k0) {
        if (FIRST) {
#pragma unroll
            for (int ro = 0; ro < 8; ro++) {
                int m = ro * 16 + a_r1;
                la1[ro] = make_float4(0.f, 0.f, 0.f, 0.f);
                int tk = stok[m];
                if (tk >= 0)
                    la1[ro] = *reinterpret_cast<const float4*>(
                        Apf + (size_t)tk * KDIM + k0 + a_c1);
            }
        } else {
#pragma unroll
            for (int ro = 0; ro < 4; ro++) {
                int m = ro * 32 + a_r2;
                la2[ro] = make_uint4(0u, 0u, 0u, 0u);
                if (m0 + m < cnt)
                    la2[ro] = *reinterpret_cast<const uint4*>(
                        Aph + (size_t)(base + m0 + m) * KDIM + k0 + a_c2);
            }
        }
#pragma unroll
        for (int ro = 0; ro < 4; ro++) {
            const float* brow = Bp + (size_t)(k0 + ro * 8 + b_r) * NDIM + n0 + b_c;
            lb[ro][0] = *reinterpret_cast<const float4*>(brow);
            lb[ro][1] = *reinterpret_cast<const float4*>(brow + 64);
        }
    };

    auto store_tile = [&](char* stage) {
        __half* As = reinterpret_cast<__half*>(stage);
        __half* Bs = reinterpret_cast<__half*>(stage + A_STAGE_B);
        if (FIRST) {
#pragma unroll
            for (int ro = 0; ro < 8; ro++) {
                int m = ro * 16 + a_r1;
                uint2 u;
                u.x = pack_h2(la1[ro].x, la1[ro].y);
                u.y = pack_h2(la1[ro].z, la1[ro].w);
                *reinterpret_cast<uint2*>(As + m * SA + a_c1) = u;
            }
        } else {
#pragma unroll
            for (int ro = 0; ro < 4; ro++) {
                int m = ro * 32 + a_r2;
                *reinterpret_cast<uint4*>(As + m * SA + a_c2) = la2[ro];
            }
        }
#pragma unroll
        for (int ro = 0; ro < 4; ro++) {
            int kl = ro * 8 + b_r;
#pragma unroll
            for (int h = 0; h < 2; h++) {
                uint2 u;
                u.x = pack_h2(lb[ro][h].x, lb[ro][h].y);
                u.y = pack_h2(lb[ro][h].z, lb[ro][h].w);
                *reinterpret_cast<uint2*>(Bs + kl * SB + h * 64 + b_c) = u;
            }
        }
    };

    // ---- prologue ----
    load_tile(kbeg);
    store_tile(dsm);
    __syncthreads();

    const int KT = (KDIM / KSPLIT) / BK;
    for (int kt = 0; kt < KT; kt++) {
        const int cur = kt & 1;
        const uint32_t a_base = sb + cur * STAGE_B + a_lm;
        const uint32_t b_base = sb + cur * STAGE_B + A_STAGE_B + b_lm;
        const bool more = (kt + 1 < KT);

        // issue next tile's global loads first (latency covered by kk=0 mmas)
        if (more) load_tile(kbeg + (kt + 1) * BK);

        uint32_t af[4][4], bf[8][2];

        // ---- kk = 0 chunk ----
#pragma unroll
        for (int mi = 0; mi < 4; mi++)
            ldsm_x4(a_base + (uint32_t)((mi * 16 * SA) * 2),
                    af[mi][0], af[mi][1], af[mi][2], af[mi][3]);
#pragma unroll
        for (int nj = 0; nj < 4; nj++)
            ldsm_x4_t(b_base + (uint32_t)((nj * 16) * 2),
                      bf[2 * nj][0], bf[2 * nj][1], bf[2 * nj + 1][0], bf[2 * nj + 1][1]);
#pragma unroll
        for (int mi = 0; mi < 4; mi++)
#pragma unroll
            for (int ni = 0; ni < 8; ni++)
                mma_f16(acc[mi][ni], af[mi], bf[ni]);

        // ---- kk = 16 chunk: ldmatrix, then STS of next stage, then mma ----
#pragma unroll
        for (int mi = 0; mi < 4; mi++)
            ldsm_x4(a_base + (uint32_t)((mi * 16 * SA + 16) * 2),
                    af[mi][0], af[mi][1], af[mi][2], af[mi][3]);
#pragma unroll
        for (int nj = 0; nj < 4; nj++)
            ldsm_x4_t(b_base + (uint32_t)((16 * SB + nj * 16) * 2),
                      bf[2 * nj][0], bf[2 * nj][1], bf[2 * nj + 1][0], bf[2 * nj + 1][1]);

        if (more) store_tile(dsm + (cur ^ 1) * STAGE_B);

#pragma unroll
        for (int mi = 0; mi < 4; mi++)
#pragma unroll
            for (int ni = 0; ni < 8; ni++)
                mma_f16(acc[mi][ni], af[mi], bf[ni]);

        __syncthreads();
    }

    // ---- epilogue: per-warp 64x64 smem transpose, coalesced writes ----
    float* scr = reinterpret_cast<float*>(dsm) + wid * 64 * EPI_STRIDE;
#pragma unroll
    for (int mi = 0; mi < 4; mi++)
#pragma unroll
        for (int ni = 0; ni < 8; ni++)
#pragma unroll
            for (int r = 0; r < 4; r++) {
                int rr = mi * 16 + gq + ((r >= 2) ? 8 : 0);
                int cc = ni * 8 + 2 * tg + (r & 1);
                scr[rr * EPI_STRIDE + cc] = acc[mi][ni][r];
            }
    __syncwarp();

    const int gcol = n0 + wn * 64 + 2 * lane;
    float2 bv = make_float2(0.f, 0.f);
    if (FIRST || ks == 0)
        bv = *reinterpret_cast<const float2*>(bias + (size_t)e * NDIM + gcol);

#pragma unroll 4
    for (int rr = 0; rr < 64; rr++) {
        int slot = m0 + wm * 64 + rr;
        if (slot < cnt) {
            float2 v = *reinterpret_cast<const float2*>(&scr[rr * EPI_STRIDE + 2 * lane]);
            v.x += bv.x; v.y += bv.y;
            if (FIRST) {
                __half2 hv = __floats2half2_rn(fmaxf(v.x, 0.0f), fmaxf(v.y, 0.0f));
                *reinterpret_cast<__half2*>(
                    g_h + (size_t)(base + slot) * NDIM + gcol) = hv;
            } else {
                float wg = g_slot_weight[base + slot];
                int   tk = g_slot_token[base + slot];
                atomicAdd(out + (size_t)tk * NDIM + gcol,     wg * v.x);
                atomicAdd(out + (size_t)tk * NDIM + gcol + 1, wg * v.y);
            }
        }
    }
}

// ---------------- launch ----------------
extern "C" void kernel_launch(void* const* d_in, const int* in_sizes, int n_in,
                              void* d_out, int out_size) {
    (void)in_sizes; (void)n_in;
    const float* x  = (const float*)d_in[0];
    const float* gw = (const float*)d_in[1];
    const float* gb = (const float*)d_in[2];
    const float* w1 = (const float*)d_in[3];
    const float* b1 = (const float*)d_in[4];
    const float* w2 = (const float*)d_in[5];
    const float* b2 = (const float*)d_in[6];
    float* out = (float*)d_out;

    static bool ready = false;
    static void* meta_addr = nullptr;
    if (!ready) {
        cudaFuncSetAttribute(moe_gemm_kernel<DDIM, HDIM, true, 1>,
                             cudaFuncAttributeMaxDynamicSharedMemorySize, SMEM_GEMM_BYTES);
        cudaFuncSetAttribute(moe_gemm_kernel<HDIM, ODIM, false, 2>,
                             cudaFuncAttributeMaxDynamicSharedMemorySize, SMEM_GEMM_BYTES);
        cudaGetSymbolAddress(&meta_addr, g_meta);
        ready = true;
    }

    cudaMemsetAsync(out, 0, (size_t)out_size * sizeof(float), 0);
    cudaMemsetAsync(meta_addr, 0, sizeof(int) * 2 * NEXP, 0);
    gate_kernel<<<NTOK / 8, 256>>>(x, gw, gb);
    scatter_kernel<<<NTOK / 256, 256>>>();

    dim3 g1(HDIM / BN, NTOK / BM, NEXP);       // (32, 64, 8)
    moe_gemm_kernel<DDIM, HDIM, true, 1><<<g1, 128, SMEM_GEMM_BYTES>>>(x, w1, b1, nullptr);

    dim3 g2(ODIM / BN, NTOK / BM, NEXP * 2);   // (8, 64, 16) split-K=2
    moe_gemm_kernel<HDIM, ODIM, false, 2><<<g2, 128, SMEM_GEMM_BYTES>>>(nullptr, w2, b2, out);
}

// round 13
// speedup vs baseline: 1.1241x; 1.1241x over previous
#include <cuda_runtime.h>
#include <cuda_fp16.h>
#include <math.h>
#include <stdint.h>

// ---------------- problem constants ----------------
#define NTOK 8192
#define DDIM 1024
#define HDIM 4096
#define ODIM 1024
#define NEXP 8
#define TOPK 3
#define NSLOT (NTOK * TOPK)

// ---------------- static device scratch ----------------
// g_meta[0..NEXP) = per-expert counts; g_meta[NEXP..2*NEXP) = scatter cursors
__device__ int    g_meta[2 * NEXP];
__device__ int    g_topk_e[NTOK * TOPK];
__device__ float  g_topk_w[NTOK * TOPK];
__device__ int    g_slot_token[NSLOT];
__device__ float  g_slot_weight[NSLOT];
__device__ __half g_h[(size_t)NSLOT * HDIM];          // 201.3 MB
__device__ __half g_xh[(size_t)NTOK * DDIM];          // 16.8 MB  (x in fp16)
__device__ __half g_w1h[(size_t)NEXP * DDIM * HDIM];  // 67.1 MB
__device__ __half g_w2h[(size_t)NEXP * HDIM * ODIM];  // 67.1 MB

// ---------------- helpers ----------------
__device__ __forceinline__ uint32_t smem_u32(const void* p) {
    uint32_t a;
    asm("{ .reg .u64 t; cvta.to.shared.u64 t, %1; cvt.u32.u64 %0, t; }"
        : "=r"(a) : "l"(p));
    return a;
}

__device__ __forceinline__ uint32_t pack_h2(float lo, float hi) {
    __half2 h = __floats2half2_rn(lo, hi);
    return *reinterpret_cast<uint32_t*>(&h);
}

__device__ __forceinline__ void ldsm_x4(uint32_t addr, uint32_t& r0, uint32_t& r1,
                                        uint32_t& r2, uint32_t& r3) {
    asm volatile("ldmatrix.sync.aligned.m8n8.x4.shared.b16 {%0,%1,%2,%3}, [%4];"
                 : "=r"(r0), "=r"(r1), "=r"(r2), "=r"(r3) : "r"(addr));
}

__device__ __forceinline__ void ldsm_x4_t(uint32_t addr, uint32_t& r0, uint32_t& r1,
                                          uint32_t& r2, uint32_t& r3) {
    asm volatile("ldmatrix.sync.aligned.m8n8.x4.trans.shared.b16 {%0,%1,%2,%3}, [%4];"
                 : "=r"(r0), "=r"(r1), "=r"(r2), "=r"(r3) : "r"(addr));
}

__device__ __forceinline__ void mma_f16(float* d, const uint32_t* a, const uint32_t* b) {
    asm volatile(
        "mma.sync.aligned.m16n8k16.row.col.f32.f16.f16.f32 "
        "{%0,%1,%2,%3}, {%4,%5,%6,%7}, {%8,%9}, {%0,%1,%2,%3};\n"
        : "+f"(d[0]), "+f"(d[1]), "+f"(d[2]), "+f"(d[3])
        : "r"(a[0]), "r"(a[1]), "r"(a[2]), "r"(a[3]),
          "r"(b[0]), "r"(b[1]));
}

__device__ __forceinline__ int expert_base(int e) {
    int b = 0;
#pragma unroll
    for (int i = 0; i < NEXP; i++)
        if (i < e) b += g_meta[i];
    return b;
}

// ---------------- weight fp32 -> fp16 conversion (grid-stride) ----------------
__global__ void cvt_kernel(const float4* __restrict__ src, uint2* __restrict__ dst, int n4) {
    for (int i = blockIdx.x * blockDim.x + threadIdx.x; i < n4;
         i += gridDim.x * blockDim.x) {
        float4 v = src[i];
        uint2 u;
        u.x = pack_h2(v.x, v.y);
        u.y = pack_h2(v.z, v.w);
        dst[i] = u;
    }
}

// ---------------- gate: one warp per token; also emits x in fp16 ----------------
__global__ void gate_kernel(const float* __restrict__ x,
                            const float* __restrict__ gw,
                            const float* __restrict__ gb) {
    int tok  = (blockIdx.x * blockDim.x + threadIdx.x) >> 5;
    int lane = threadIdx.x & 31;
    if (tok >= NTOK) return;

    const float4* xr4 = reinterpret_cast<const float4*>(x + (size_t)tok * DDIM);

    float4 xv[8];
#pragma unroll
    for (int j = 0; j < 8; j++) xv[j] = xr4[j * 32 + lane];

    // free x -> fp16 conversion (row already in registers)
    uint2* xh2 = reinterpret_cast<uint2*>(g_xh + (size_t)tok * DDIM);
#pragma unroll
    for (int j = 0; j < 8; j++) {
        uint2 u;
        u.x = pack_h2(xv[j].x, xv[j].y);
        u.y = pack_h2(xv[j].z, xv[j].w);
        xh2[j * 32 + lane] = u;
    }

    float part[NEXP];
#pragma unroll
    for (int e = 0; e < NEXP; e++) part[e] = 0.0f;

#pragma unroll
    for (int j = 0; j < 8; j++) {
        const int d0 = j * 128 + lane * 4;
        const float xq[4] = { xv[j].x, xv[j].y, xv[j].z, xv[j].w };
#pragma unroll
        for (int q = 0; q < 4; q++) {
            const float4* gp = reinterpret_cast<const float4*>(gw + (size_t)(d0 + q) * NEXP);
            float4 a = gp[0];
            float4 b = gp[1];
            part[0] += xq[q] * a.x; part[1] += xq[q] * a.y;
            part[2] += xq[q] * a.z; part[3] += xq[q] * a.w;
            part[4] += xq[q] * b.x; part[5] += xq[q] * b.y;
            part[6] += xq[q] * b.z; part[7] += xq[q] * b.w;
        }
    }
#pragma unroll
    for (int off = 16; off > 0; off >>= 1)
#pragma unroll
        for (int e = 0; e < NEXP; e++)
            part[e] += __shfl_xor_sync(0xffffffffu, part[e], off);

    if (lane == 0) {
        float s[NEXP];
#pragma unroll
        for (int e = 0; e < NEXP; e++) s[e] = part[e] + gb[e];

        int id[TOPK];
        bool used[NEXP];
#pragma unroll
        for (int e = 0; e < NEXP; e++) used[e] = false;
#pragma unroll
        for (int k = 0; k < TOPK; k++) {
            float best = -1e30f;
            int bi = 0;
#pragma unroll
            for (int e = 0; e < NEXP; e++)
                if (!used[e] && s[e] > best) { best = s[e]; bi = e; }
            used[bi] = true;
            id[k] = bi;
        }

        float mx = s[0];
#pragma unroll
        for (int e = 1; e < NEXP; e++) mx = fmaxf(mx, s[e]);
        float p[NEXP], tot = 0.0f;
#pragma unroll
        for (int e = 0; e < NEXP; e++) { p[e] = expf(s[e] - mx); tot += p[e]; }
        float inv = 1.0f / tot;
        float msum = (p[id[0]] + p[id[1]] + p[id[2]]) * inv;
        float den = msum + 1e-8f;

#pragma unroll
        for (int k = 0; k < TOPK; k++) {
            int e = id[k];
            g_topk_e[tok * TOPK + k] = e;
            g_topk_w[tok * TOPK + k] = (p[e] * inv) / den;
            atomicAdd(&g_meta[e], 1);
        }
    }
}

// ---------------- scatter tokens into compact per-expert lists ----------------
__global__ void scatter_kernel() {
    int t = blockIdx.x * blockDim.x + threadIdx.x;
    if (t >= NTOK) return;
#pragma unroll
    for (int k = 0; k < TOPK; k++) {
        int e = g_topk_e[t * TOPK + k];
        int pos = atomicAdd(&g_meta[NEXP + e], 1);
        int i = expert_base(e) + pos;
        g_slot_token[i] = t;
        g_slot_weight[i] = g_topk_w[t * TOPK + k];
    }
}

// ---------------- fp16 mma.sync grouped GEMM, all-fp16 operands ----------------
// CTA 128x128, 4 warps of 64x64, K-tile 32, double-buffered, ldmatrix fragments.
// All GMEM operands fp16 -> staging is pure uint4 copy (halved L1TEX LDG traffic).
#define BM 128
#define BN 128
#define BK 32
#define SA 40     // A row stride (halves)
#define SB 136    // B row stride (halves)
#define A_STAGE_B (BM * SA * 2)              // 10240 bytes
#define B_STAGE_B (BK * SB * 2)              // 8704 bytes
#define STAGE_B (A_STAGE_B + B_STAGE_B)      // 18944 bytes
#define EPI_STRIDE 66
#define SMEM_GEMM_BYTES (4 * 64 * EPI_STRIDE * 4)   // 67584 (> 2*STAGE_B = 37888)

template <int KDIM, int NDIM, bool FIRST, int KSPLIT>
__global__ __launch_bounds__(128, 2) void moe_gemm_kernel(
    const __half* __restrict__ Bh,   // g_w1h / g_w2h  [E, KDIM, NDIM] fp16
    const float* __restrict__ bias,  // [E, NDIM] fp32
    float* __restrict__ out)
{
    const int zz = blockIdx.z;
    const int e  = zz / KSPLIT;
    const int ks = zz % KSPLIT;
    const int cnt = g_meta[e];
    const int m0 = blockIdx.y * BM;
    if (m0 >= cnt) return;
    const int base = expert_base(e);
    const int n0 = blockIdx.x * BN;
    const int kbeg = ks * (KDIM / KSPLIT);

    extern __shared__ char dsm[];
    __shared__ int stok[BM];
    const uint32_t sb = smem_u32(dsm);

    const int tid  = threadIdx.x;
    const int wid  = tid >> 5;
    const int lane = tid & 31;
    const int gq = lane >> 2;   // 0..7
    const int tg = lane & 3;    // 0..3
    const int wm = wid >> 1;    // 0..1
    const int wn = wid & 1;     // 0..1

    if (FIRST) {
        if (tid < BM) {
            int r = m0 + tid;
            stok[tid] = (r < cnt) ? g_slot_token[base + r] : -1;
        }
    }
    __syncthreads();

    const __half* Ap = FIRST ? g_xh : g_h;
    const __half* Bp = Bh + (size_t)e * KDIM * NDIM;

    // staging maps (128 threads), all uint4 fp16 copies
    const int a_r  = tid >> 2;            // row in 32-row group (0..31)
    const int a_ch = (tid & 3) * 8;       // k offset (halves): 0,8,16,24
    const int b_r  = tid >> 4;            // B row in 8-row group (0..7)
    const int b_ch = (tid & 15) * 8;      // B col offset (halves): 0..120

    // ldmatrix lane offsets (bytes within stage)
    const uint32_t a_lm = (uint32_t)(((wm * 64 + (lane & 15)) * SA + ((lane >> 4) << 3)) * 2);
    const uint32_t b_lm = (uint32_t)(((lane & 15) * SB + wn * 64 + ((lane >> 4) << 3)) * 2);

    float acc[4][8][4];
#pragma unroll
    for (int mi = 0; mi < 4; mi++)
#pragma unroll
        for (int ni = 0; ni < 8; ni++)
#pragma unroll
            for (int r = 0; r < 4; r++) acc[mi][ni][r] = 0.0f;

    // staging registers
    uint4 la[4];   // A: 4 rounds x 32 rows
    uint4 lb[4];   // B: 4 rounds x 8 rows

    auto load_tile = [&](int k0) {
#pragma unroll
        for (int ro = 0; ro < 4; ro++) {
            int m = ro * 32 + a_r;
            la[ro] = make_uint4(0u, 0u, 0u, 0u);
            if (FIRST) {
                int tk = stok[m];
                if (tk >= 0)
                    la[ro] = *reinterpret_cast<const uint4*>(
                        Ap + (size_t)tk * KDIM + k0 + a_ch);
            } else {
                if (m0 + m < cnt)
                    la[ro] = *reinterpret_cast<const uint4*>(
                        Ap + (size_t)(base + m0 + m) * KDIM + k0 + a_ch);
            }
        }
#pragma unroll
        for (int ro = 0; ro < 4; ro++)
            lb[ro] = *reinterpret_cast<const uint4*>(
                Bp + (size_t)(k0 + ro * 8 + b_r) * NDIM + n0 + b_ch);
    };

    auto store_tile = [&](char* stage) {
        __half* As = reinterpret_cast<__half*>(stage);
        __half* Bs = reinterpret_cast<__half*>(stage + A_STAGE_B);
#pragma unroll
        for (int ro = 0; ro < 4; ro++) {
            int m = ro * 32 + a_r;
            *reinterpret_cast<uint4*>(As + m * SA + a_ch) = la[ro];
        }
#pragma unroll
        for (int ro = 0; ro < 4; ro++)
            *reinterpret_cast<uint4*>(Bs + (ro * 8 + b_r) * SB + b_ch) = lb[ro];
    };

    // ---- prologue ----
    load_tile(kbeg);
    store_tile(dsm);
    __syncthreads();

    const int KT = (KDIM / KSPLIT) / BK;
    for (int kt = 0; kt < KT; kt++) {
        const int cur = kt & 1;
        const uint32_t a_base = sb + cur * STAGE_B + a_lm;
        const uint32_t b_base = sb + cur * STAGE_B + A_STAGE_B + b_lm;
        const bool more = (kt + 1 < KT);

        // issue next tile's global loads first (latency covered by kk=0 mmas)
        if (more) load_tile(kbeg + (kt + 1) * BK);

        uint32_t af[4][4], bf[8][2];

        // ---- kk = 0 chunk ----
#pragma unroll
        for (int mi = 0; mi < 4; mi++)
            ldsm_x4(a_base + (uint32_t)((mi * 16 * SA) * 2),
                    af[mi][0], af[mi][1], af[mi][2], af[mi][3]);
#pragma unroll
        for (int nj = 0; nj < 4; nj++)
            ldsm_x4_t(b_base + (uint32_t)((nj * 16) * 2),
                      bf[2 * nj][0], bf[2 * nj][1], bf[2 * nj + 1][0], bf[2 * nj + 1][1]);
#pragma unroll
        for (int mi = 0; mi < 4; mi++)
#pragma unroll
            for (int ni = 0; ni < 8; ni++)
                mma_f16(acc[mi][ni], af[mi], bf[ni]);

        // ---- kk = 16 chunk: ldmatrix, then STS of next stage, then mma ----
#pragma unroll
        for (int mi = 0; mi < 4; mi++)
            ldsm_x4(a_base + (uint32_t)((mi * 16 * SA + 16) * 2),
                    af[mi][0], af[mi][1], af[mi][2], af[mi][3]);
#pragma unroll
        for (int nj = 0; nj < 4; nj++)
            ldsm_x4_t(b_base + (uint32_t)((16 * SB + nj * 16) * 2),
                      bf[2 * nj][0], bf[2 * nj][1], bf[2 * nj + 1][0], bf[2 * nj + 1][1]);

        if (more) store_tile(dsm + (cur ^ 1) * STAGE_B);

#pragma unroll
        for (int mi = 0; mi < 4; mi++)
#pragma unroll
            for (int ni = 0; ni < 8; ni++)
                mma_f16(acc[mi][ni], af[mi], bf[ni]);

        __syncthreads();
    }

    // ---- epilogue: per-warp 64x64 smem transpose, coalesced writes ----
    float* scr = reinterpret_cast<float*>(dsm) + wid * 64 * EPI_STRIDE;
#pragma unroll
    for (int mi = 0; mi < 4; mi++)
#pragma unroll
        for (int ni = 0; ni < 8; ni++)
#pragma unroll
            for (int r = 0; r < 4; r++) {
                int rr = mi * 16 + gq + ((r >= 2) ? 8 : 0);
                int cc = ni * 8 + 2 * tg + (r & 1);
                scr[rr * EPI_STRIDE + cc] = acc[mi][ni][r];
            }
    __syncwarp();

    const int gcol = n0 + wn * 64 + 2 * lane;
    float2 bv = make_float2(0.f, 0.f);
    if (FIRST || ks == 0)
        bv = *reinterpret_cast<const float2*>(bias + (size_t)e * NDIM + gcol);

#pragma unroll 4
    for (int rr = 0; rr < 64; rr++) {
        int slot = m0 + wm * 64 + rr;
        if (slot < cnt) {
            float2 v = *reinterpret_cast<const float2*>(&scr[rr * EPI_STRIDE + 2 * lane]);
            v.x += bv.x; v.y += bv.y;
            if (FIRST) {
                __half2 hv = __floats2half2_rn(fmaxf(v.x, 0.0f), fmaxf(v.y, 0.0f));
                *reinterpret_cast<__half2*>(
                    g_h + (size_t)(base + slot) * NDIM + gcol) = hv;
            } else {
                float wg = g_slot_weight[base + slot];
                int   tk = g_slot_token[base + slot];
                atomicAdd(out + (size_t)tk * NDIM + gcol,     wg * v.x);
                atomicAdd(out + (size_t)tk * NDIM + gcol + 1, wg * v.y);
            }
        }
    }
}

// ---------------- launch ----------------
extern "C" void kernel_launch(void* const* d_in, const int* in_sizes, int n_in,
                              void* d_out, int out_size) {
    (void)in_sizes; (void)n_in;
    const float* x  = (const float*)d_in[0];
    const float* gw = (const float*)d_in[1];
    const float* gb = (const float*)d_in[2];
    const float* w1 = (const float*)d_in[3];
    const float* b1 = (const float*)d_in[4];
    const float* w2 = (const float*)d_in[5];
    const float* b2 = (const float*)d_in[6];
    float* out = (float*)d_out;

    static bool ready = false;
    static void* meta_addr = nullptr;
    static void* w1h_addr = nullptr;
    static void* w2h_addr = nullptr;
    if (!ready) {
        cudaFuncSetAttribute(moe_gemm_kernel<DDIM, HDIM, true, 1>,
                             cudaFuncAttributeMaxDynamicSharedMemorySize, SMEM_GEMM_BYTES);
        cudaFuncSetAttribute(moe_gemm_kernel<HDIM, ODIM, false, 2>,
                             cudaFuncAttributeMaxDynamicSharedMemorySize, SMEM_GEMM_BYTES);
        cudaGetSymbolAddress(&meta_addr, g_meta);
        cudaGetSymbolAddress(&w1h_addr, g_w1h);
        cudaGetSymbolAddress(&w2h_addr, g_w2h);
        ready = true;
    }

    cudaMemsetAsync(out, 0, (size_t)out_size * sizeof(float), 0);
    cudaMemsetAsync(meta_addr, 0, sizeof(int) * 2 * NEXP, 0);

    const int W_N4 = NEXP * DDIM * HDIM / 4;   // 8.39M float4 each
    cvt_kernel<<<4096, 256>>>((const float4*)w1, (uint2*)w1h_addr, W_N4);
    cvt_kernel<<<4096, 256>>>((const float4*)w2, (uint2*)w2h_addr, W_N4);

    gate_kernel<<<NTOK / 8, 256>>>(x, gw, gb);
    scatter_kernel<<<NTOK / 256, 256>>>();

    dim3 g1(HDIM / BN, NTOK / BM, NEXP);       // (32, 64, 8)
    moe_gemm_kernel<DDIM, HDIM, true, 1>
        <<<g1, 128, SMEM_GEMM_BYTES>>>((const __half*)w1h_addr, b1, nullptr);

    dim3 g2(ODIM / BN, NTOK / BM, NEXP * 2);   // (8, 64, 16) split-K=2
    moe_gemm_kernel<HDIM, ODIM, false, 2>
        <<<g2, 128, SMEM_GEMM_BYTES>>>((const __half*)w2h_addr, b2, out);
}

// round 14
// speedup vs baseline: 1.2471x; 1.1094x over previous
#include <cuda_runtime.h>
#include <cuda_fp16.h>
#include <math.h>
#include <stdint.h>

// ---------------- problem constants ----------------
#define NTOK 8192
#define DDIM 1024
#define HDIM 4096
#define ODIM 1024
#define NEXP 8
#define TOPK 3
#define NSLOT (NTOK * TOPK)

// ---------------- static device scratch ----------------
__device__ int    g_meta[2 * NEXP];     // [0,8): counts  [8,16): scatter cursors
__device__ int    g_topk_e[NTOK * TOPK];
__device__ float  g_topk_w[NTOK * TOPK];
__device__ int    g_slot_token[NSLOT];
__device__ float  g_slot_weight[NSLOT];
__device__ __half g_h[(size_t)NSLOT * HDIM];          // 201.3 MB
__device__ __half g_xh[(size_t)NTOK * DDIM];          // 16.8 MB
__device__ __half g_w1h[(size_t)NEXP * DDIM * HDIM];  // 67.1 MB
__device__ __half g_w2h[(size_t)NEXP * HDIM * ODIM];  // 67.1 MB

// ---------------- helpers ----------------
__device__ __forceinline__ uint32_t smem_u32(const void* p) {
    uint32_t a;
    asm("{ .reg .u64 t; cvta.to.shared.u64 t, %1; cvt.u32.u64 %0, t; }"
        : "=r"(a) : "l"(p));
    return a;
}

__device__ __forceinline__ uint32_t pack_h2(float lo, float hi) {
    __half2 h = __floats2half2_rn(lo, hi);
    return *reinterpret_cast<uint32_t*>(&h);
}

__device__ __forceinline__ void ldsm_x4(uint32_t addr, uint32_t& r0, uint32_t& r1,
                                        uint32_t& r2, uint32_t& r3) {
    asm volatile("ldmatrix.sync.aligned.m8n8.x4.shared.b16 {%0,%1,%2,%3}, [%4];"
                 : "=r"(r0), "=r"(r1), "=r"(r2), "=r"(r3) : "r"(addr));
}

__device__ __forceinline__ void ldsm_x4_t(uint32_t addr, uint32_t& r0, uint32_t& r1,
                                          uint32_t& r2, uint32_t& r3) {
    asm volatile("ldmatrix.sync.aligned.m8n8.x4.trans.shared.b16 {%0,%1,%2,%3}, [%4];"
                 : "=r"(r0), "=r"(r1), "=r"(r2), "=r"(r3) : "r"(addr));
}

__device__ __forceinline__ void mma_f16(float* d, const uint32_t* a, const uint32_t* b) {
    asm volatile(
        "mma.sync.aligned.m16n8k16.row.col.f32.f16.f16.f32 "
        "{%0,%1,%2,%3}, {%4,%5,%6,%7}, {%8,%9}, {%0,%1,%2,%3};\n"
        : "+f"(d[0]), "+f"(d[1]), "+f"(d[2]), "+f"(d[3])
        : "r"(a[0]), "r"(a[1]), "r"(a[2]), "r"(a[3]),
          "r"(b[0]), "r"(b[1]));
}

// 16B async copy; szc = 16 (copy) or 0 (zero-fill destination)
__device__ __forceinline__ void cp_async16(uint32_t dst, const void* src, int szc) {
    asm volatile("cp.async.cg.shared.global [%0], [%1], 16, %2;"
                 :: "r"(dst), "l"(src), "r"(szc) : "memory");
}
#define CP_COMMIT() asm volatile("cp.async.commit_group;" ::: "memory")
#define CP_WAIT1()  asm volatile("cp.async.wait_group 1;" ::: "memory")

__device__ __forceinline__ int expert_base(int e) {
    int b = 0;
#pragma unroll
    for (int i = 0; i < NEXP; i++)
        if (i < e) b += g_meta[i];
    return b;
}

// ---------------- weight fp32 -> fp16 conversion (grid-stride) ----------------
__global__ void cvt_kernel(const float4* __restrict__ src, uint2* __restrict__ dst, int n4) {
    for (int i = blockIdx.x * blockDim.x + threadIdx.x; i < n4;
         i += gridDim.x * blockDim.x) {
        float4 v = src[i];
        uint2 u;
        u.x = pack_h2(v.x, v.y);
        u.y = pack_h2(v.z, v.w);
        dst[i] = u;
    }
}

// ---------------- gate: one warp per token; also emits x in fp16 ----------------
__global__ void gate_kernel(const float* __restrict__ x,
                            const float* __restrict__ gw,
                            const float* __restrict__ gb) {
    int tok  = (blockIdx.x * blockDim.x + threadIdx.x) >> 5;
    int lane = threadIdx.x & 31;
    if (tok >= NTOK) return;

    const float4* xr4 = reinterpret_cast<const float4*>(x + (size_t)tok * DDIM);

    float4 xv[8];
#pragma unroll
    for (int j = 0; j < 8; j++) xv[j] = xr4[j * 32 + lane];

    uint2* xh2 = reinterpret_cast<uint2*>(g_xh + (size_t)tok * DDIM);
#pragma unroll
    for (int j = 0; j < 8; j++) {
        uint2 u;
        u.x = pack_h2(xv[j].x, xv[j].y);
        u.y = pack_h2(xv[j].z, xv[j].w);
        xh2[j * 32 + lane] = u;
    }

    float part[NEXP];
#pragma unroll
    for (int e = 0; e < NEXP; e++) part[e] = 0.0f;

#pragma unroll
    for (int j = 0; j < 8; j++) {
        const int d0 = j * 128 + lane * 4;
        const float xq[4] = { xv[j].x, xv[j].y, xv[j].z, xv[j].w };
#pragma unroll
        for (int q = 0; q < 4; q++) {
            const float4* gp = reinterpret_cast<const float4*>(gw + (size_t)(d0 + q) * NEXP);
            float4 a = gp[0];
            float4 b = gp[1];
            part[0] += xq[q] * a.x; part[1] += xq[q] * a.y;
            part[2] += xq[q] * a.z; part[3] += xq[q] * a.w;
            part[4] += xq[q] * b.x; part[5] += xq[q] * b.y;
            part[6] += xq[q] * b.z; part[7] += xq[q] * b.w;
        }
    }
#pragma unroll
    for (int off = 16; off > 0; off >>= 1)
#pragma unroll
        for (int e = 0; e < NEXP; e++)
            part[e] += __shfl_xor_sync(0xffffffffu, part[e], off);

    if (lane == 0) {
        float s[NEXP];
#pragma unroll
        for (int e = 0; e < NEXP; e++) s[e] = part[e] + gb[e];

        int id[TOPK];
        bool used[NEXP];
#pragma unroll
        for (int e = 0; e < NEXP; e++) used[e] = false;
#pragma unroll
        for (int k = 0; k < TOPK; k++) {
            float best = -1e30f;
            int bi = 0;
#pragma unroll
            for (int e = 0; e < NEXP; e++)
                if (!used[e] && s[e] > best) { best = s[e]; bi = e; }
            used[bi] = true;
            id[k] = bi;
        }

        float mx = s[0];
#pragma unroll
        for (int e = 1; e < NEXP; e++) mx = fmaxf(mx, s[e]);
        float p[NEXP], tot = 0.0f;
#pragma unroll
        for (int e = 0; e < NEXP; e++) { p[e] = expf(s[e] - mx); tot += p[e]; }
        float inv = 1.0f / tot;
        float msum = (p[id[0]] + p[id[1]] + p[id[2]]) * inv;
        float den = msum + 1e-8f;

#pragma unroll
        for (int k = 0; k < TOPK; k++) {
            int e = id[k];
            g_topk_e[tok * TOPK + k] = e;
            g_topk_w[tok * TOPK + k] = (p[e] * inv) / den;
            atomicAdd(&g_meta[e], 1);
        }
    }
}

// ---------------- scatter tokens into compact per-expert lists ----------------
__global__ void scatter_kernel() {
    int t = blockIdx.x * blockDim.x + threadIdx.x;
    if (t >= NTOK) return;
#pragma unroll
    for (int k = 0; k < TOPK; k++) {
        int e = g_topk_e[t * TOPK + k];
        int pos = atomicAdd(&g_meta[NEXP + e], 1);
        int i = expert_base(e) + pos;
        g_slot_token[i] = t;
        g_slot_weight[i] = g_topk_w[t * TOPK + k];
    }
}

// ---------------- fp16 mma.sync grouped GEMM, cp.async 3-stage pipeline ----------------
#define BM 128
#define BN 128
#define BK 32
#define SA 40     // A row stride (halves)
#define SB 136    // B row stride (halves)
#define A_STAGE_B (BM * SA * 2)              // 10240 bytes
#define B_STAGE_B (BK * SB * 2)              // 8704 bytes
#define STAGE_B (A_STAGE_B + B_STAGE_B)      // 18944 bytes
#define NSTAGE 3
#define EPI_STRIDE 66
#define SMEM_GEMM_BYTES (4 * 64 * EPI_STRIDE * 4)   // 67584 (> 3*STAGE_B = 56832)

template <int KDIM, int NDIM, bool FIRST, int KSPLIT>
__global__ __launch_bounds__(128, 2) void moe_gemm_kernel(
    const __half* __restrict__ Bh,   // g_w1h / g_w2h  [E, KDIM, NDIM] fp16
    const float* __restrict__ bias,  // [E, NDIM] fp32
    float* __restrict__ out)
{
    const int zz = blockIdx.z;
    const int e  = zz / KSPLIT;
    const int ks = zz % KSPLIT;
    const int cnt = g_meta[e];
    const int m0 = blockIdx.y * BM;
    if (m0 >= cnt) return;
    const int base = expert_base(e);
    const int n0 = blockIdx.x * BN;
    const int kbeg = ks * (KDIM / KSPLIT);

    extern __shared__ char dsm[];
    __shared__ int stok[BM];
    const uint32_t sb = smem_u32(dsm);

    const int tid  = threadIdx.x;
    const int wid  = tid >> 5;
    const int lane = tid & 31;
    const int gq = lane >> 2;
    const int tg = lane & 3;
    const int wm = wid >> 1;
    const int wn = wid & 1;

    if (FIRST) {
        if (tid < BM) {
            int r = m0 + tid;
            stok[tid] = (r < cnt) ? g_slot_token[base + r] : -1;
        }
    }
    __syncthreads();

    const __half* Ap = FIRST ? g_xh : g_h;
    const __half* Bp = Bh + (size_t)e * KDIM * NDIM;

    // staging maps (128 threads), 16B cp.async each
    const int a_r  = tid >> 2;            // row in 32-row group (0..31)
    const int a_ch = (tid & 3) * 8;       // k offset (halves)
    const int b_r  = tid >> 4;            // B row in 8-row group (0..7)
    const int b_ch = (tid & 15) * 8;      // B col offset (halves)

    // per-thread A row sources (row index / validity fixed across k)
    const __half* a_src[4];
    int a_sz[4];
#pragma unroll
    for (int ro = 0; ro < 4; ro++) {
        int m = ro * 32 + a_r;
        if (FIRST) {
            int tk = stok[m];
            a_src[ro] = Ap + (size_t)(tk < 0 ? 0 : tk) * KDIM + a_ch;
            a_sz[ro] = (tk >= 0) ? 16 : 0;
        } else {
            bool ok = (m0 + m < cnt);
            a_src[ro] = Ap + (size_t)(base + (ok ? m0 + m : 0)) * KDIM + a_ch;
            a_sz[ro] = ok ? 16 : 0;
        }
    }

    // ldmatrix lane offsets (bytes within stage)
    const uint32_t a_lm = (uint32_t)(((wm * 64 + (lane & 15)) * SA + ((lane >> 4) << 3)) * 2);
    const uint32_t b_lm = (uint32_t)(((lane & 15) * SB + wn * 64 + ((lane >> 4) << 3)) * 2);

    float acc[4][8][4];
#pragma unroll
    for (int mi = 0; mi < 4; mi++)
#pragma unroll
        for (int ni = 0; ni < 8; ni++)
#pragma unroll
            for (int r = 0; r < 4; r++) acc[mi][ni][r] = 0.0f;

    const int KT = (KDIM / KSPLIT) / BK;

    // issue one k-tile's copies into stage s (does NOT commit)
    auto issue_tile = [&](int s, int k0) {
        const uint32_t as = sb + s * STAGE_B;
        const uint32_t bs = as + A_STAGE_B;
#pragma unroll
        for (int ro = 0; ro < 4; ro++) {
            int m = ro * 32 + a_r;
            cp_async16(as + (uint32_t)((m * SA + a_ch) * 2), a_src[ro] + k0, a_sz[ro]);
        }
#pragma unroll
        for (int ro = 0; ro < 4; ro++) {
            cp_async16(bs + (uint32_t)(((ro * 8 + b_r) * SB + b_ch) * 2),
                       Bp + (size_t)(k0 + ro * 8 + b_r) * NDIM + n0 + b_ch, 16);
        }
    };

    // ---- prologue: stages 0 and 1 in flight ----
    issue_tile(0, kbeg);
    CP_COMMIT();
    if (KT > 1) issue_tile(1, kbeg + BK);
    CP_COMMIT();

    for (int kt = 0; kt < KT; kt++) {
        const int cur = kt % NSTAGE;

        CP_WAIT1();          // all groups but the newest done -> stage kt resident
        __syncthreads();     // all warps' copies visible; stage (kt-1) fully consumed

        // keep the group cadence: commit every iteration (empty group when done)
        if (kt + 2 < KT) issue_tile((kt + 2) % NSTAGE, kbeg + (kt + 2) * BK);
        CP_COMMIT();

        const uint32_t a_base = sb + cur * STAGE_B + a_lm;
        const uint32_t b_base = sb + cur * STAGE_B + A_STAGE_B + b_lm;

        uint32_t af[4][4], bf[8][2];
#pragma unroll
        for (int kk = 0; kk < BK; kk += 16) {
#pragma unroll
            for (int mi = 0; mi < 4; mi++)
                ldsm_x4(a_base + (uint32_t)((mi * 16 * SA + kk) * 2),
                        af[mi][0], af[mi][1], af[mi][2], af[mi][3]);
#pragma unroll
            for (int nj = 0; nj < 4; nj++)
                ldsm_x4_t(b_base + (uint32_t)((kk * SB + nj * 16) * 2),
                          bf[2 * nj][0], bf[2 * nj][1], bf[2 * nj + 1][0], bf[2 * nj + 1][1]);
#pragma unroll
            for (int mi = 0; mi < 4; mi++)
#pragma unroll
                for (int ni = 0; ni < 8; ni++)
                    mma_f16(acc[mi][ni], af[mi], bf[ni]);
        }
    }
    __syncthreads();

    // ---- epilogue: per-warp 64x64 smem transpose, coalesced writes ----
    float* scr = reinterpret_cast<float*>(dsm) + wid * 64 * EPI_STRIDE;
#pragma unroll
    for (int mi = 0; mi < 4; mi++)
#pragma unroll
        for (int ni = 0; ni < 8; ni++)
#pragma unroll
            for (int r = 0; r < 4; r++) {
                int rr = mi * 16 + gq + ((r >= 2) ? 8 : 0);
                int cc = ni * 8 + 2 * tg + (r & 1);
                scr[rr * EPI_STRIDE + cc] = acc[mi][ni][r];
            }
    __syncwarp();

    const int gcol = n0 + wn * 64 + 2 * lane;
    float2 bv = make_float2(0.f, 0.f);
    if (FIRST || ks == 0)
        bv = *reinterpret_cast<const float2*>(bias + (size_t)e * NDIM + gcol);

#pragma unroll 4
    for (int rr = 0; rr < 64; rr++) {
        int slot = m0 + wm * 64 + rr;
        if (slot < cnt) {
            float2 v = *reinterpret_cast<const float2*>(&scr[rr * EPI_STRIDE + 2 * lane]);
            v.x += bv.x; v.y += bv.y;
            if (FIRST) {
                __half2 hv = __floats2half2_rn(fmaxf(v.x, 0.0f), fmaxf(v.y, 0.0f));
                *reinterpret_cast<__half2*>(
                    g_h + (size_t)(base + slot) * NDIM + gcol) = hv;
            } else {
                float wg = g_slot_weight[base + slot];
                int   tk = g_slot_token[base + slot];
                atomicAdd(out + (size_t)tk * NDIM + gcol,     wg * v.x);
                atomicAdd(out + (size_t)tk * NDIM + gcol + 1, wg * v.y);
            }
        }
    }
}

// ---------------- launch ----------------
extern "C" void kernel_launch(void* const* d_in, const int* in_sizes, int n_in,
                              void* d_out, int out_size) {
    (void)in_sizes; (void)n_in;
    const float* x  = (const float*)d_in[0];
    const float* gw = (const float*)d_in[1];
    const float* gb = (const float*)d_in[2];
    const float* w1 = (const float*)d_in[3];
    const float* b1 = (const float*)d_in[4];
    const float* w2 = (const float*)d_in[5];
    const float* b2 = (const float*)d_in[6];
    float* out = (float*)d_out;

    static bool ready = false;
    static void* meta_addr = nullptr;
    static void* w1h_addr = nullptr;
    static void* w2h_addr = nullptr;
    if (!ready) {
        cudaFuncSetAttribute(moe_gemm_kernel<DDIM, HDIM, true, 1>,
                             cudaFuncAttributeMaxDynamicSharedMemorySize, SMEM_GEMM_BYTES);
        cudaFuncSetAttribute(moe_gemm_kernel<HDIM, ODIM, false, 2>,
                             cudaFuncAttributeMaxDynamicSharedMemorySize, SMEM_GEMM_BYTES);
        cudaGetSymbolAddress(&meta_addr, g_meta);
        cudaGetSymbolAddress(&w1h_addr, g_w1h);
        cudaGetSymbolAddress(&w2h_addr, g_w2h);
        ready = true;
    }

    cudaMemsetAsync(out, 0, (size_t)out_size * sizeof(float), 0);
    cudaMemsetAsync(meta_addr, 0, sizeof(int) * 2 * NEXP, 0);

    const int W_N4 = NEXP * DDIM * HDIM / 4;
    cvt_kernel<<<4096, 256>>>((const float4*)w1, (uint2*)w1h_addr, W_N4);
    cvt_kernel<<<4096, 256>>>((const float4*)w2, (uint2*)w2h_addr, W_N4);

    gate_kernel<<<NTOK / 8, 256>>>(x, gw, gb);
    scatter_kernel<<<NTOK / 256, 256>>>();

    dim3 g1(HDIM / BN, NTOK / BM, NEXP);       // (32, 64, 8)
    moe_gemm_kernel<DDIM, HDIM, true, 1>
        <<<g1, 128, SMEM_GEMM_BYTES>>>((const __half*)w1h_addr, b1, nullptr);

    dim3 g2(ODIM / BN, NTOK / BM, NEXP * 2);   // (8, 64, 16) split-K=2
    moe_gemm_kernel<HDIM, ODIM, false, 2>
        <<<g2, 128, SMEM_GEMM_BYTES>>>((const __half*)w2h_addr, b2, out);
}

// round 15
// speedup vs baseline: 1.3093x; 1.0499x over previous
#include <cuda_runtime.h>
#include <cuda_fp16.h>
#include <math.h>
#include <stdint.h>

// ---------------- problem constants ----------------
#define NTOK 8192
#define DDIM 1024
#define HDIM 4096
#define ODIM 1024
#define NEXP 8
#define TOPK 3
#define NSLOT (NTOK * TOPK)

// ---------------- static device scratch ----------------
__device__ int    g_meta[2 * NEXP];     // [0,8): counts  [8,16): scatter cursors
__device__ int    g_topk_e[NTOK * TOPK];
__device__ float  g_topk_w[NTOK * TOPK];
__device__ int    g_slot_token[NSLOT];
__device__ float  g_slot_weight[NSLOT];
__device__ __half g_h[(size_t)NSLOT * HDIM];          // 201.3 MB
__device__ __half g_xh[(size_t)NTOK * DDIM];          // 16.8 MB
__device__ __half g_w1h[(size_t)NEXP * DDIM * HDIM];  // 67.1 MB
__device__ __half g_w2h[(size_t)NEXP * HDIM * ODIM];  // 67.1 MB

// ---------------- helpers ----------------
__device__ __forceinline__ uint32_t smem_u32(const void* p) {
    uint32_t a;
    asm("{ .reg .u64 t; cvta.to.shared.u64 t, %1; cvt.u32.u64 %0, t; }"
        : "=r"(a) : "l"(p));
    return a;
}

__device__ __forceinline__ uint32_t pack_h2(float lo, float hi) {
    __half2 h = __floats2half2_rn(lo, hi);
    return *reinterpret_cast<uint32_t*>(&h);
}

__device__ __forceinline__ void ldsm_x4(uint32_t addr, uint32_t& r0, uint32_t& r1,
                                        uint32_t& r2, uint32_t& r3) {
    asm volatile("ldmatrix.sync.aligned.m8n8.x4.shared.b16 {%0,%1,%2,%3}, [%4];"
                 : "=r"(r0), "=r"(r1), "=r"(r2), "=r"(r3) : "r"(addr));
}

__device__ __forceinline__ void ldsm_x4_t(uint32_t addr, uint32_t& r0, uint32_t& r1,
                                          uint32_t& r2, uint32_t& r3) {
    asm volatile("ldmatrix.sync.aligned.m8n8.x4.trans.shared.b16 {%0,%1,%2,%3}, [%4];"
                 : "=r"(r0), "=r"(r1), "=r"(r2), "=r"(r3) : "r"(addr));
}

__device__ __forceinline__ void mma_f16(float* d, const uint32_t* a, const uint32_t* b) {
    asm volatile(
        "mma.sync.aligned.m16n8k16.row.col.f32.f16.f16.f32 "
        "{%0,%1,%2,%3}, {%4,%5,%6,%7}, {%8,%9}, {%0,%1,%2,%3};\n"
        : "+f"(d[0]), "+f"(d[1]), "+f"(d[2]), "+f"(d[3])
        : "r"(a[0]), "r"(a[1]), "r"(a[2]), "r"(a[3]),
          "r"(b[0]), "r"(b[1]));
}

// 16B async copy; szc = 16 (copy) or 0 (zero-fill destination)
__device__ __forceinline__ void cp_async16(uint32_t dst, const void* src, int szc) {
    asm volatile("cp.async.cg.shared.global [%0], [%1], 16, %2;"
                 :: "r"(dst), "l"(src), "r"(szc) : "memory");
}
#define CP_COMMIT() asm volatile("cp.async.commit_group;" ::: "memory")
#define CP_WAIT1()  asm volatile("cp.async.wait_group 1;" ::: "memory")
#define CP_WAIT2()  asm volatile("cp.async.wait_group 2;" ::: "memory")

__device__ __forceinline__ int expert_base(int e) {
    int b = 0;
#pragma unroll
    for (int i = 0; i < NEXP; i++)
        if (i < e) b += g_meta[i];
    return b;
}

// ---------------- weight fp32 -> fp16 conversion (both weights, one launch) ----------------
__global__ void cvt_kernel(const float4* __restrict__ s1, uint2* __restrict__ d1,
                           const float4* __restrict__ s2, uint2* __restrict__ d2, int n4) {
    for (int i = blockIdx.x * blockDim.x + threadIdx.x; i < n4;
         i += gridDim.x * blockDim.x) {
        float4 v = s1[i];
        uint2 u;
        u.x = pack_h2(v.x, v.y);
        u.y = pack_h2(v.z, v.w);
        d1[i] = u;
        float4 w = s2[i];
        uint2 t;
        t.x = pack_h2(w.x, w.y);
        t.y = pack_h2(w.z, w.w);
        d2[i] = t;
    }
}

// ---------------- gate: one warp per token; also emits x in fp16 ----------------
__global__ void gate_kernel(const float* __restrict__ x,
                            const float* __restrict__ gw,
                            const float* __restrict__ gb) {
    int tok  = (blockIdx.x * blockDim.x + threadIdx.x) >> 5;
    int lane = threadIdx.x & 31;
    if (tok >= NTOK) return;

    const float4* xr4 = reinterpret_cast<const float4*>(x + (size_t)tok * DDIM);

    float4 xv[8];
#pragma unroll
    for (int j = 0; j < 8; j++) xv[j] = xr4[j * 32 + lane];

    uint2* xh2 = reinterpret_cast<uint2*>(g_xh + (size_t)tok * DDIM);
#pragma unroll
    for (int j = 0; j < 8; j++) {
        uint2 u;
        u.x = pack_h2(xv[j].x, xv[j].y);
        u.y = pack_h2(xv[j].z, xv[j].w);
        xh2[j * 32 + lane] = u;
    }

    float part[NEXP];
#pragma unroll
    for (int e = 0; e < NEXP; e++) part[e] = 0.0f;

#pragma unroll
    for (int j = 0; j < 8; j++) {
        const int d0 = j * 128 + lane * 4;
        const float xq[4] = { xv[j].x, xv[j].y, xv[j].z, xv[j].w };
#pragma unroll
        for (int q = 0; q < 4; q++) {
            const float4* gp = reinterpret_cast<const float4*>(gw + (size_t)(d0 + q) * NEXP);
            float4 a = gp[0];
            float4 b = gp[1];
            part[0] += xq[q] * a.x; part[1] += xq[q] * a.y;
            part[2] += xq[q] * a.z; part[3] += xq[q] * a.w;
            part[4] += xq[q] * b.x; part[5] += xq[q] * b.y;
            part[6] += xq[q] * b.z; part[7] += xq[q] * b.w;
        }
    }
#pragma unroll
    for (int off = 16; off > 0; off >>= 1)
#pragma unroll
        for (int e = 0; e < NEXP; e++)
            part[e] += __shfl_xor_sync(0xffffffffu, part[e], off);

    if (lane == 0) {
        float s[NEXP];
#pragma unroll
        for (int e = 0; e < NEXP; e++) s[e] = part[e] + gb[e];

        int id[TOPK];
        bool used[NEXP];
#pragma unroll
        for (int e = 0; e < NEXP; e++) used[e] = false;
#pragma unroll
        for (int k = 0; k < TOPK; k++) {
            float best = -1e30f;
            int bi = 0;
#pragma unroll
            for (int e = 0; e < NEXP; e++)
                if (!used[e] && s[e] > best) { best = s[e]; bi = e; }
            used[bi] = true;
            id[k] = bi;
        }

        float mx = s[0];
#pragma unroll
        for (int e = 1; e < NEXP; e++) mx = fmaxf(mx, s[e]);
        float p[NEXP], tot = 0.0f;
#pragma unroll
        for (int e = 0; e < NEXP; e++) { p[e] = expf(s[e] - mx); tot += p[e]; }
        float inv = 1.0f / tot;
        float msum = (p[id[0]] + p[id[1]] + p[id[2]]) * inv;
        float den = msum + 1e-8f;

#pragma unroll
        for (int k = 0; k < TOPK; k++) {
            int e = id[k];
            g_topk_e[tok * TOPK + k] = e;
            g_topk_w[tok * TOPK + k] = (p[e] * inv) / den;
            atomicAdd(&g_meta[e], 1);
        }
    }
}

// ---------------- scatter tokens into compact per-expert lists ----------------
__global__ void scatter_kernel() {
    int t = blockIdx.x * blockDim.x + threadIdx.x;
    if (t >= NTOK) return;
#pragma unroll
    for (int k = 0; k < TOPK; k++) {
        int e = g_topk_e[t * TOPK + k];
        int pos = atomicAdd(&g_meta[NEXP + e], 1);
        int i = expert_base(e) + pos;
        g_slot_token[i] = t;
        g_slot_weight[i] = g_topk_w[t * TOPK + k];
    }
}

// ---------------- fp16 mma.sync grouped GEMM ----------------
// cp.async 4-stage smem ring + 2-deep register fragment pipeline:
// every ldsm batch is covered by a full 32-mma chunk.
#define BM 128
#define BN 128
#define BK 32
#define SA 40     // A row stride (halves)
#define SB 136    // B row stride (halves)
#define A_STAGE_B (BM * SA * 2)              // 10240 bytes
#define B_STAGE_B (BK * SB * 2)              // 8704 bytes
#define STAGE_B (A_STAGE_B + B_STAGE_B)      // 18944 bytes
#define NSTAGE 4
#define EPI_STRIDE 66
#define EPI_BYTES (4 * 64 * EPI_STRIDE * 4)              // 67584
#define RING_BYTES (NSTAGE * STAGE_B)                    // 75776
#define SMEM_GEMM_BYTES (RING_BYTES > EPI_BYTES ? RING_BYTES : EPI_BYTES)

template <int KDIM, int NDIM, bool FIRST, int KSPLIT>
__global__ __launch_bounds__(128, 2) void moe_gemm_kernel(
    const __half* __restrict__ Bh,   // g_w1h / g_w2h  [E, KDIM, NDIM] fp16
    const float* __restrict__ bias,  // [E, NDIM] fp32
    float* __restrict__ out)
{
    const int zz = blockIdx.z;
    const int e  = zz / KSPLIT;
    const int ks = zz % KSPLIT;
    const int cnt = g_meta[e];
    const int m0 = blockIdx.y * BM;
    if (m0 >= cnt) return;
    const int base = expert_base(e);
    const int n0 = blockIdx.x * BN;
    const int kbeg = ks * (KDIM / KSPLIT);

    extern __shared__ char dsm[];
    __shared__ int stok[BM];
    const uint32_t sb = smem_u32(dsm);

    const int tid  = threadIdx.x;
    const int wid  = tid >> 5;
    const int lane = tid & 31;
    const int gq = lane >> 2;
    const int tg = lane & 3;
    const int wm = wid >> 1;
    const int wn = wid & 1;

    if (FIRST) {
        if (tid < BM) {
            int r = m0 + tid;
            stok[tid] = (r < cnt) ? g_slot_token[base + r] : -1;
        }
    }
    __syncthreads();

    const __half* Ap = FIRST ? g_xh : g_h;
    const __half* Bp = Bh + (size_t)e * KDIM * NDIM;

    // staging maps (128 threads), 16B cp.async each
    const int a_r  = tid >> 2;            // row in 32-row group (0..31)
    const int a_ch = (tid & 3) * 8;       // k offset (halves)
    const int b_r  = tid >> 4;            // B row in 8-row group (0..7)
    const int b_ch = (tid & 15) * 8;      // B col offset (halves)

    // per-thread A row sources (fixed across k)
    const __half* a_src[4];
    int a_sz[4];
#pragma unroll
    for (int ro = 0; ro < 4; ro++) {
        int m = ro * 32 + a_r;
        if (FIRST) {
            int tk = stok[m];
            a_src[ro] = Ap + (size_t)(tk < 0 ? 0 : tk) * KDIM + a_ch;
            a_sz[ro] = (tk >= 0) ? 16 : 0;
        } else {
            bool ok = (m0 + m < cnt);
            a_src[ro] = Ap + (size_t)(base + (ok ? m0 + m : 0)) * KDIM + a_ch;
            a_sz[ro] = ok ? 16 : 0;
        }
    }

    // ldmatrix lane offsets (bytes within stage)
    const uint32_t a_lm = (uint32_t)(((wm * 64 + (lane & 15)) * SA + ((lane >> 4) << 3)) * 2);
    const uint32_t b_lm = (uint32_t)(((lane & 15) * SB + wn * 64 + ((lane >> 4) << 3)) * 2);

    float acc[4][8][4];
#pragma unroll
    for (int mi = 0; mi < 4; mi++)
#pragma unroll
        for (int ni = 0; ni < 8; ni++)
#pragma unroll
            for (int r = 0; r < 4; r++) acc[mi][ni][r] = 0.0f;

    const int KT = (KDIM / KSPLIT) / BK;

    auto issue_tile = [&](int s, int k0) {
        const uint32_t as = sb + s * STAGE_B;
        const uint32_t bs = as + A_STAGE_B;
#pragma unroll
        for (int ro = 0; ro < 4; ro++) {
            int m = ro * 32 + a_r;
            cp_async16(as + (uint32_t)((m * SA + a_ch) * 2), a_src[ro] + k0, a_sz[ro]);
        }
#pragma unroll
        for (int ro = 0; ro < 4; ro++) {
            cp_async16(bs + (uint32_t)(((ro * 8 + b_r) * SB + b_ch) * 2),
                       Bp + (size_t)(k0 + ro * 8 + b_r) * NDIM + n0 + b_ch, 16);
        }
    };

    auto lda = [&](uint32_t (&af)[4][4], int s, int kk) {
        const uint32_t ab = sb + s * STAGE_B + a_lm;
#pragma unroll
        for (int mi = 0; mi < 4; mi++)
            ldsm_x4(ab + (uint32_t)((mi * 16 * SA + kk) * 2),
                    af[mi][0], af[mi][1], af[mi][2], af[mi][3]);
    };
    auto ldb = [&](uint32_t (&bf)[8][2], int s, int kk) {
        const uint32_t bb = sb + s * STAGE_B + A_STAGE_B + b_lm;
#pragma unroll
        for (int nj = 0; nj < 4; nj++)
            ldsm_x4_t(bb + (uint32_t)((kk * SB + nj * 16) * 2),
                      bf[2 * nj][0], bf[2 * nj][1], bf[2 * nj + 1][0], bf[2 * nj + 1][1]);
    };

    // ---- prologue: 3 stages in flight; preload tile0 kk=0 fragments ----
    issue_tile(0, kbeg);
    CP_COMMIT();
    if (KT > 1) issue_tile(1, kbeg + BK);
    CP_COMMIT();
    if (KT > 2) issue_tile(2, kbeg + 2 * BK);
    CP_COMMIT();

    uint32_t af0[4][4], bf0[8][2], af1[4][4], bf1[8][2];

    CP_WAIT2();          // stage 0 resident
    __syncthreads();
    lda(af0, 0, 0);
    ldb(bf0, 0, 0);

    for (int kt = 0; kt < KT; kt++) {
        const int cur = kt % NSTAGE;
        const int nxt = (kt + 1) % NSTAGE;

        CP_WAIT1();          // stages kt and kt+1 resident (newest group may pend)
        __syncthreads();     // visibility; stage (kt+3)%4 fully consumed

        if (kt + 3 < KT) issue_tile((kt + 3) % NSTAGE, kbeg + (kt + 3) * BK);
        CP_COMMIT();         // keep group cadence (empty at tail)

        // load kk=16 fragments, then mma kk=0 chunk
        lda(af1, cur, 16);
        ldb(bf1, cur, 16);
#pragma unroll
        for (int mi = 0; mi < 4; mi++)
#pragma unroll
            for (int ni = 0; ni < 8; ni++)
                mma_f16(acc[mi][ni], af0[mi], bf0[ni]);

        // prefetch next tile's kk=0 fragments, then mma kk=16 chunk
        // (last iteration reads stale smem; results discarded)
        lda(af0, nxt, 0);
        ldb(bf0, nxt, 0);
#pragma unroll
        for (int mi = 0; mi < 4; mi++)
#pragma unroll
            for (int ni = 0; ni < 8; ni++)
                mma_f16(acc[mi][ni], af1[mi], bf1[ni]);
    }
    __syncthreads();

    // ---- epilogue: per-warp 64x64 smem transpose, coalesced writes ----
    float* scr = reinterpret_cast<float*>(dsm) + wid * 64 * EPI_STRIDE;
#pragma unroll
    for (int mi = 0; mi < 4; mi++)
#pragma unroll
        for (int ni = 0; ni < 8; ni++)
#pragma unroll
            for (int r = 0; r < 4; r++) {
                int rr = mi * 16 + gq + ((r >= 2) ? 8 : 0);
                int cc = ni * 8 + 2 * tg + (r & 1);
                scr[rr * EPI_STRIDE + cc] = acc[mi][ni][r];
            }
    __syncwarp();

    const int gcol = n0 + wn * 64 + 2 * lane;
    float2 bv = make_float2(0.f, 0.f);
    if (FIRST || ks == 0)
        bv = *reinterpret_cast<const float2*>(bias + (size_t)e * NDIM + gcol);

#pragma unroll 4
    for (int rr = 0; rr < 64; rr++) {
        int slot = m0 + wm * 64 + rr;
        if (slot < cnt) {
            float2 v = *reinterpret_cast<const float2*>(&scr[rr * EPI_STRIDE + 2 * lane]);
            v.x += bv.x; v.y += bv.y;
            if (FIRST) {
                __half2 hv = __floats2half2_rn(fmaxf(v.x, 0.0f), fmaxf(v.y, 0.0f));
                *reinterpret_cast<__half2*>(
                    g_h + (size_t)(base + slot) * NDIM + gcol) = hv;
            } else {
                float wg = g_slot_weight[base + slot];
                int   tk = g_slot_token[base + slot];
                atomicAdd(out + (size_t)tk * NDIM + gcol,     wg * v.x);
                atomicAdd(out + (size_t)tk * NDIM + gcol + 1, wg * v.y);
            }
        }
    }
}

// ---------------- launch ----------------
extern "C" void kernel_launch(void* const* d_in, const int* in_sizes, int n_in,
                              void* d_out, int out_size) {
    (void)in_sizes; (void)n_in;
    const float* x  = (const float*)d_in[0];
    const float* gw = (const float*)d_in[1];
    const float* gb = (const float*)d_in[2];
    const float* w1 = (const float*)d_in[3];
    const float* b1 = (const float*)d_in[4];
    const float* w2 = (const float*)d_in[5];
    const float* b2 = (const float*)d_in[6];
    float* out = (float*)d_out;

    static bool ready = false;
    static void* meta_addr = nullptr;
    static void* w1h_addr = nullptr;
    static void* w2h_addr = nullptr;
    if (!ready) {
        cudaFuncSetAttribute(moe_gemm_kernel<DDIM, HDIM, true, 1>,
                             cudaFuncAttributeMaxDynamicSharedMemorySize, SMEM_GEMM_BYTES);
        cudaFuncSetAttribute(moe_gemm_kernel<HDIM, ODIM, false, 2>,
                             cudaFuncAttributeMaxDynamicSharedMemorySize, SMEM_GEMM_BYTES);
        cudaGetSymbolAddress(&meta_addr, g_meta);
        cudaGetSymbolAddress(&w1h_addr, g_w1h);
        cudaGetSymbolAddress(&w2h_addr, g_w2h);
        ready = true;
    }

    cudaMemsetAsync(out, 0, (size_t)out_size * sizeof(float), 0);
    cudaMemsetAsync(meta_addr, 0, sizeof(int) * 2 * NEXP, 0);

    const int W_N4 = NEXP * DDIM * HDIM / 4;
    cvt_kernel<<<4096, 256>>>((const float4*)w1, (uint2*)w1h_addr,
                              (const float4*)w2, (uint2*)w2h_addr, W_N4);

    gate_kernel<<<NTOK / 8, 256>>>(x, gw, gb);
    scatter_kernel<<<NTOK / 256, 256>>>();

    dim3 g1(HDIM / BN, NTOK / BM, NEXP);       // (32, 64, 8)
    moe_gemm_kernel<DDIM, HDIM, true, 1>
        <<<g1, 128, SMEM_GEMM_BYTES>>>((const __half*)w1h_addr, b1, nullptr);

    dim3 g2(ODIM / BN, NTOK / BM, NEXP * 2);   // (8, 64, 16) split-K=2
    moe_gemm_kernel<HDIM, ODIM, false, 2>
        <<<g2, 128, SMEM_GEMM_BYTES>>>((const __half*)w2h_addr, b2, out);
}

// round 16
// speedup vs baseline: 1.3203x; 1.0084x over previous
#include <cuda_runtime.h>
#include <cuda_fp16.h>
#include <math.h>
#include <stdint.h>

// ---------------- problem constants ----------------
#define NTOK 8192
#define DDIM 1024
#define HDIM 4096
#define ODIM 1024
#define NEXP 8
#define TOPK 3
#define NSLOT (NTOK * TOPK)

// ---------------- static device scratch ----------------
__device__ int    g_meta[2 * NEXP];     // [0,8): counts  [8,16): scatter cursors
__device__ int    g_topk_e[NTOK * TOPK];
__device__ float  g_topk_w[NTOK * TOPK];
__device__ int    g_slot_token[NSLOT];
__device__ float  g_slot_weight[NSLOT];
__device__ __half g_h[(size_t)NSLOT * HDIM];          // 201.3 MB
__device__ __half g_xh[(size_t)NTOK * DDIM];          // 16.8 MB
__device__ __half g_w1h[(size_t)NEXP * DDIM * HDIM];  // 67.1 MB
__device__ __half g_w2h[(size_t)NEXP * HDIM * ODIM];  // 67.1 MB

// ---------------- helpers ----------------
__device__ __forceinline__ uint32_t smem_u32(const void* p) {
    uint32_t a;
    asm("{ .reg .u64 t; cvta.to.shared.u64 t, %1; cvt.u32.u64 %0, t; }"
        : "=r"(a) : "l"(p));
    return a;
}

__device__ __forceinline__ uint32_t pack_h2(float lo, float hi) {
    __half2 h = __floats2half2_rn(lo, hi);
    return *reinterpret_cast<uint32_t*>(&h);
}

__device__ __forceinline__ void ldsm_x4(uint32_t addr, uint32_t& r0, uint32_t& r1,
                                        uint32_t& r2, uint32_t& r3) {
    asm volatile("ldmatrix.sync.aligned.m8n8.x4.shared.b16 {%0,%1,%2,%3}, [%4];"
                 : "=r"(r0), "=r"(r1), "=r"(r2), "=r"(r3) : "r"(addr));
}

__device__ __forceinline__ void ldsm_x4_t(uint32_t addr, uint32_t& r0, uint32_t& r1,
                                          uint32_t& r2, uint32_t& r3) {
    asm volatile("ldmatrix.sync.aligned.m8n8.x4.trans.shared.b16 {%0,%1,%2,%3}, [%4];"
                 : "=r"(r0), "=r"(r1), "=r"(r2), "=r"(r3) : "r"(addr));
}

__device__ __forceinline__ void mma_f16(float* d, const uint32_t* a, const uint32_t* b) {
    asm volatile(
        "mma.sync.aligned.m16n8k16.row.col.f32.f16.f16.f32 "
        "{%0,%1,%2,%3}, {%4,%5,%6,%7}, {%8,%9}, {%0,%1,%2,%3};\n"
        : "+f"(d[0]), "+f"(d[1]), "+f"(d[2]), "+f"(d[3])
        : "r"(a[0]), "r"(a[1]), "r"(a[2]), "r"(a[3]),
          "r"(b[0]), "r"(b[1]));
}

// 16B async copy; szc = 16 (copy) or 0 (zero-fill destination)
__device__ __forceinline__ void cp_async16(uint32_t dst, const void* src, int szc) {
    asm volatile("cp.async.cg.shared.global [%0], [%1], 16, %2;"
                 :: "r"(dst), "l"(src), "r"(szc) : "memory");
}
#define CP_COMMIT() asm volatile("cp.async.commit_group;" ::: "memory")
#define CP_WAIT1()  asm volatile("cp.async.wait_group 1;" ::: "memory")
#define CP_WAIT2()  asm volatile("cp.async.wait_group 2;" ::: "memory")

__device__ __forceinline__ int expert_base(int e) {
    int b = 0;
#pragma unroll
    for (int i = 0; i < NEXP; i++)
        if (i < e) b += g_meta[i];
    return b;
}

// ---------------- fused prep: weight cvt (blocks [0,4096)) + gate (blocks [4096,5120)) ----------------
#define CVT_BLOCKS 4096
#define GATE_BLOCKS (NTOK / 8)          // 1024 (256 thr = 8 warps = 8 tokens/blk)

__global__ void prep_kernel(const float* __restrict__ x,
                            const float* __restrict__ gw,
                            const float* __restrict__ gb,
                            const float4* __restrict__ w1s, uint2* __restrict__ w1d,
                            const float4* __restrict__ w2s, uint2* __restrict__ w2d,
                            int wn4) {
    if (blockIdx.x < CVT_BLOCKS) {
        // ---- weight fp32 -> fp16 (grid-stride over both weight tensors) ----
        for (int i = blockIdx.x * blockDim.x + threadIdx.x; i < wn4;
             i += CVT_BLOCKS * blockDim.x) {
            float4 v = w1s[i];
            uint2 u;
            u.x = pack_h2(v.x, v.y);
            u.y = pack_h2(v.z, v.w);
            w1d[i] = u;
            float4 w = w2s[i];
            uint2 t;
            t.x = pack_h2(w.x, w.y);
            t.y = pack_h2(w.z, w.w);
            w2d[i] = t;
        }
        return;
    }

    // ---- gate: one warp per token; also emits x in fp16 ----
    int tok  = ((blockIdx.x - CVT_BLOCKS) * blockDim.x + threadIdx.x) >> 5;
    int lane = threadIdx.x & 31;
    if (tok >= NTOK) return;

    const float4* xr4 = reinterpret_cast<const float4*>(x + (size_t)tok * DDIM);

    float4 xv[8];
#pragma unroll
    for (int j = 0; j < 8; j++) xv[j] = xr4[j * 32 + lane];

    uint2* xh2 = reinterpret_cast<uint2*>(g_xh + (size_t)tok * DDIM);
#pragma unroll
    for (int j = 0; j < 8; j++) {
        uint2 u;
        u.x = pack_h2(xv[j].x, xv[j].y);
        u.y = pack_h2(xv[j].z, xv[j].w);
        xh2[j * 32 + lane] = u;
    }

    float part[NEXP];
#pragma unroll
    for (int e = 0; e < NEXP; e++) part[e] = 0.0f;

#pragma unroll
    for (int j = 0; j < 8; j++) {
        const float xq[4] = { xv[j].x, xv[j].y, xv[j].z, xv[j].w };
        const int d0 = j * 128 + lane * 4;
#pragma unroll
        for (int q = 0; q < 4; q++) {
            const float4* gp = reinterpret_cast<const float4*>(gw + (size_t)(d0 + q) * NEXP);
            float4 a = gp[0];
            float4 b = gp[1];
            part[0] += xq[q] * a.x; part[1] += xq[q] * a.y;
            part[2] += xq[q] * a.z; part[3] += xq[q] * a.w;
            part[4] += xq[q] * b.x; part[5] += xq[q] * b.y;
            part[6] += xq[q] * b.z; part[7] += xq[q] * b.w;
        }
    }
#pragma unroll
    for (int off = 16; off > 0; off >>= 1)
#pragma unroll
        for (int e = 0; e < NEXP; e++)
            part[e] += __shfl_xor_sync(0xffffffffu, part[e], off);

    if (lane == 0) {
        float s[NEXP];
#pragma unroll
        for (int e = 0; e < NEXP; e++) s[e] = part[e] + gb[e];

        int id[TOPK];
        bool used[NEXP];
#pragma unroll
        for (int e = 0; e < NEXP; e++) used[e] = false;
#pragma unroll
        for (int k = 0; k < TOPK; k++) {
            float best = -1e30f;
            int bi = 0;
#pragma unroll
            for (int e = 0; e < NEXP; e++)
                if (!used[e] && s[e] > best) { best = s[e]; bi = e; }
            used[bi] = true;
            id[k] = bi;
        }

        float mx = s[0];
#pragma unroll
        for (int e = 1; e < NEXP; e++) mx = fmaxf(mx, s[e]);
        float p[NEXP], tot = 0.0f;
#pragma unroll
        for (int e = 0; e < NEXP; e++) { p[e] = expf(s[e] - mx); tot += p[e]; }
        float inv = 1.0f / tot;
        float msum = (p[id[0]] + p[id[1]] + p[id[2]]) * inv;
        float den = msum + 1e-8f;

#pragma unroll
        for (int k = 0; k < TOPK; k++) {
            int e = id[k];
            g_topk_e[tok * TOPK + k] = e;
            g_topk_w[tok * TOPK + k] = (p[e] * inv) / den;
            atomicAdd(&g_meta[e], 1);
        }
    }
}

// ---------------- scatter tokens into compact per-expert lists ----------------
__global__ void scatter_kernel() {
    int t = blockIdx.x * blockDim.x + threadIdx.x;
    if (t >= NTOK) return;
#pragma unroll
    for (int k = 0; k < TOPK; k++) {
        int e = g_topk_e[t * TOPK + k];
        int pos = atomicAdd(&g_meta[NEXP + e], 1);
        int i = expert_base(e) + pos;
        g_slot_token[i] = t;
        g_slot_weight[i] = g_topk_w[t * TOPK + k];
    }
}

// ---------------- fp16 mma.sync grouped GEMM ----------------
// cp.async 4-stage smem ring + 2-deep register fragment pipeline.
#define BM 128
#define BN 128
#define BK 32
#define SA 40     // A row stride (halves)
#define SB 136    // B row stride (halves)
#define A_STAGE_B (BM * SA * 2)              // 10240 bytes
#define B_STAGE_B (BK * SB * 2)              // 8704 bytes
#define STAGE_B (A_STAGE_B + B_STAGE_B)      // 18944 bytes
#define NSTAGE 4
#define EPI_STRIDE 66
#define EPI_BYTES (4 * 64 * EPI_STRIDE * 4)              // 67584
#define RING_BYTES (NSTAGE * STAGE_B)                    // 75776
#define SMEM_GEMM_BYTES (RING_BYTES > EPI_BYTES ? RING_BYTES : EPI_BYTES)

template <int KDIM, int NDIM, bool FIRST, int KSPLIT>
__global__ __launch_bounds__(128, 2) void moe_gemm_kernel(
    const __half* __restrict__ Bh,   // g_w1h / g_w2h  [E, KDIM, NDIM] fp16
    const float* __restrict__ bias,  // [E, NDIM] fp32
    float* __restrict__ out)
{
    const int zz = blockIdx.z;
    const int e  = zz / KSPLIT;
    const int ks = zz % KSPLIT;
    const int cnt = g_meta[e];
    const int m0 = blockIdx.y * BM;
    if (m0 >= cnt) return;
    const int base = expert_base(e);
    const int n0 = blockIdx.x * BN;
    const int kbeg = ks * (KDIM / KSPLIT);

    extern __shared__ char dsm[];
    __shared__ int stok[BM];
    const uint32_t sb = smem_u32(dsm);

    const int tid  = threadIdx.x;
    const int wid  = tid >> 5;
    const int lane = tid & 31;
    const int gq = lane >> 2;
    const int tg = lane & 3;
    const int wm = wid >> 1;
    const int wn = wid & 1;

    if (FIRST) {
        if (tid < BM) {
            int r = m0 + tid;
            stok[tid] = (r < cnt) ? g_slot_token[base + r] : -1;
        }
    }
    __syncthreads();

    const __half* Ap = FIRST ? g_xh : g_h;
    const __half* Bp = Bh + (size_t)e * KDIM * NDIM;

    // staging maps (128 threads), 16B cp.async each
    const int a_r  = tid >> 2;            // row in 32-row group (0..31)
    const int a_ch = (tid & 3) * 8;       // k offset (halves)
    const int b_r  = tid >> 4;            // B row in 8-row group (0..7)
    const int b_ch = (tid & 15) * 8;      // B col offset (halves)

    // per-thread A row sources (fixed across k)
    const __half* a_src[4];
    int a_sz[4];
#pragma unroll
    for (int ro = 0; ro < 4; ro++) {
        int m = ro * 32 + a_r;
        if (FIRST) {
            int tk = stok[m];
            a_src[ro] = Ap + (size_t)(tk < 0 ? 0 : tk) * KDIM + a_ch;
            a_sz[ro] = (tk >= 0) ? 16 : 0;
        } else {
            bool ok = (m0 + m < cnt);
            a_src[ro] = Ap + (size_t)(base + (ok ? m0 + m : 0)) * KDIM + a_ch;
            a_sz[ro] = ok ? 16 : 0;
        }
    }

    // ldmatrix lane offsets (bytes within stage)
    const uint32_t a_lm = (uint32_t)(((wm * 64 + (lane & 15)) * SA + ((lane >> 4) << 3)) * 2);
    const uint32_t b_lm = (uint32_t)(((lane & 15) * SB + wn * 64 + ((lane >> 4) << 3)) * 2);

    float acc[4][8][4];
#pragma unroll
    for (int mi = 0; mi < 4; mi++)
#pragma unroll
        for (int ni = 0; ni < 8; ni++)
#pragma unroll
            for (int r = 0; r < 4; r++) acc[mi][ni][r] = 0.0f;

    const int KT = (KDIM / KSPLIT) / BK;

    auto issue_tile = [&](int s, int k0) {
        const uint32_t as = sb + s * STAGE_B;
        const uint32_t bs = as + A_STAGE_B;
#pragma unroll
        for (int ro = 0; ro < 4; ro++) {
            int m = ro * 32 + a_r;
            cp_async16(as + (uint32_t)((m * SA + a_ch) * 2), a_src[ro] + k0, a_sz[ro]);
        }
#pragma unroll
        for (int ro = 0; ro < 4; ro++) {
            cp_async16(bs + (uint32_t)(((ro * 8 + b_r) * SB + b_ch) * 2),
                       Bp + (size_t)(k0 + ro * 8 + b_r) * NDIM + n0 + b_ch, 16);
        }
    };

    auto lda = [&](uint32_t (&af)[4][4], int s, int kk) {
        const uint32_t ab = sb + s * STAGE_B + a_lm;
#pragma unroll
        for (int mi = 0; mi < 4; mi++)
            ldsm_x4(ab + (uint32_t)((mi * 16 * SA + kk) * 2),
                    af[mi][0], af[mi][1], af[mi][2], af[mi][3]);
    };
    auto ldb = [&](uint32_t (&bf)[8][2], int s, int kk) {
        const uint32_t bb = sb + s * STAGE_B + A_STAGE_B + b_lm;
#pragma unroll
        for (int nj = 0; nj < 4; nj++)
            ldsm_x4_t(bb + (uint32_t)((kk * SB + nj * 16) * 2),
                      bf[2 * nj][0], bf[2 * nj][1], bf[2 * nj + 1][0], bf[2 * nj + 1][1]);
    };

    // ---- prologue: 3 stages in flight; preload tile0 kk=0 fragments ----
    issue_tile(0, kbeg);
    CP_COMMIT();
    if (KT > 1) issue_tile(1, kbeg + BK);
    CP_COMMIT();
    if (KT > 2) issue_tile(2, kbeg + 2 * BK);
    CP_COMMIT();

    uint32_t af0[4][4], bf0[8][2], af1[4][4], bf1[8][2];

    CP_WAIT2();          // stage 0 resident
    __syncthreads();
    lda(af0, 0, 0);
    ldb(bf0, 0, 0);

    for (int kt = 0; kt < KT; kt++) {
        const int cur = kt % NSTAGE;
        const int nxt = (kt + 1) % NSTAGE;

        CP_WAIT1();          // stages kt and kt+1 resident (newest group may pend)
        __syncthreads();     // visibility; stage (kt+3)%4 fully consumed

        if (kt + 3 < KT) issue_tile((kt + 3) % NSTAGE, kbeg + (kt + 3) * BK);
        CP_COMMIT();         // keep group cadence (empty at tail)

        // load kk=16 fragments, then mma kk=0 chunk
        lda(af1, cur, 16);
        ldb(bf1, cur, 16);
#pragma unroll
        for (int mi = 0; mi < 4; mi++)
#pragma unroll
            for (int ni = 0; ni < 8; ni++)
                mma_f16(acc[mi][ni], af0[mi], bf0[ni]);

        // prefetch next tile's kk=0 fragments, then mma kk=16 chunk
        // (last iteration reads stale smem; results discarded)
        lda(af0, nxt, 0);
        ldb(bf0, nxt, 0);
#pragma unroll
        for (int mi = 0; mi < 4; mi++)
#pragma unroll
            for (int ni = 0; ni < 8; ni++)
                mma_f16(acc[mi][ni], af1[mi], bf1[ni]);
    }
    __syncthreads();

    // ---- epilogue: per-warp 64x64 smem transpose, coalesced writes ----
    float* scr = reinterpret_cast<float*>(dsm) + wid * 64 * EPI_STRIDE;
#pragma unroll
    for (int mi = 0; mi < 4; mi++)
#pragma unroll
        for (int ni = 0; ni < 8; ni++)
#pragma unroll
            for (int r = 0; r < 4; r++) {
                int rr = mi * 16 + gq + ((r >= 2) ? 8 : 0);
                int cc = ni * 8 + 2 * tg + (r & 1);
                scr[rr * EPI_STRIDE + cc] = acc[mi][ni][r];
            }
    __syncwarp();

    const int gcol = n0 + wn * 64 + 2 * lane;
    float2 bv = make_float2(0.f, 0.f);
    if (FIRST || ks == 0)
        bv = *reinterpret_cast<const float2*>(bias + (size_t)e * NDIM + gcol);

#pragma unroll 4
    for (int rr = 0; rr < 64; rr++) {
        int slot = m0 + wm * 64 + rr;
        if (slot < cnt) {
            float2 v = *reinterpret_cast<const float2*>(&scr[rr * EPI_STRIDE + 2 * lane]);
            v.x += bv.x; v.y += bv.y;
            if (FIRST) {
                __half2 hv = __floats2half2_rn(fmaxf(v.x, 0.0f), fmaxf(v.y, 0.0f));
                *reinterpret_cast<__half2*>(
                    g_h + (size_t)(base + slot) * NDIM + gcol) = hv;
            } else {
                float wg = g_slot_weight[base + slot];
                int   tk = g_slot_token[base + slot];
                atomicAdd(out + (size_t)tk * NDIM + gcol,     wg * v.x);
                atomicAdd(out + (size_t)tk * NDIM + gcol + 1, wg * v.y);
            }
        }
    }
}

// ---------------- launch ----------------
extern "C" void kernel_launch(void* const* d_in, const int* in_sizes, int n_in,
                              void* d_out, int out_size) {
    (void)in_sizes; (void)n_in;
    const float* x  = (const float*)d_in[0];
    const float* gw = (const float*)d_in[1];
    const float* gb = (const float*)d_in[2];
    const float* w1 = (const float*)d_in[3];
    const float* b1 = (const float*)d_in[4];
    const float* w2 = (const float*)d_in[5];
    const float* b2 = (const float*)d_in[6];
    float* out = (float*)d_out;

    static bool ready = false;
    static void* meta_addr = nullptr;
    static void* w1h_addr = nullptr;
    static void* w2h_addr = nullptr;
    if (!ready) {
        cudaFuncSetAttribute(moe_gemm_kernel<DDIM, HDIM, true, 1>,
                             cudaFuncAttributeMaxDynamicSharedMemorySize, SMEM_GEMM_BYTES);
        cudaFuncSetAttribute(moe_gemm_kernel<HDIM, ODIM, false, 2>,
                             cudaFuncAttributeMaxDynamicSharedMemorySize, SMEM_GEMM_BYTES);
        cudaGetSymbolAddress(&meta_addr, g_meta);
        cudaGetSymbolAddress(&w1h_addr, g_w1h);
        cudaGetSymbolAddress(&w2h_addr, g_w2h);
        ready = true;
    }

    cudaMemsetAsync(out, 0, (size_t)out_size * sizeof(float), 0);
    cudaMemsetAsync(meta_addr, 0, sizeof(int) * 2 * NEXP, 0);

    const int W_N4 = NEXP * DDIM * HDIM / 4;
    prep_kernel<<<CVT_BLOCKS + GATE_BLOCKS, 256>>>(
        x, gw, gb,
        (const float4*)w1, (uint2*)w1h_addr,
        (const float4*)w2, (uint2*)w2h_addr, W_N4);

    scatter_kernel<<<NTOK / 256, 256>>>();

    dim3 g1(HDIM / BN, NTOK / BM, NEXP);       // (32, 64, 8)
    moe_gemm_kernel<DDIM, HDIM, true, 1>
        <<<g1, 128, SMEM_GEMM_BYTES>>>((const __half*)w1h_addr, b1, nullptr);

    dim3 g2(ODIM / BN, NTOK / BM, NEXP * 2);   // (8, 64, 16) split-K=2
    moe_gemm_kernel<HDIM, ODIM, false, 2>
        <<<g2, 128, SMEM_GEMM_BYTES>>>((const __half*)w2h_addr, b2, out);
}